// round 8
// baseline (speedup 1.0000x reference)
#include <cuda_runtime.h>

#define VOCAB 500
#define EMB   64
#define HID   64
#define BATCH 512
#define SEQ   512
#define ROWS_PER_CTA 4    // 2 groups x 2 interleaved row-streams per thread
#define HPAD  68          // padded h row: [0..31] jh0, [36..67] jh1

// Precomputed input projection: E'[v][i] = b_ih0[i] + sum_j emb[v][j]*W_ih0[i][j]
__device__ float g_xproj[VOCAB * HID];

typedef unsigned long long u64;

__device__ __forceinline__ void fma2(u64 &d, u64 a, u64 b) {
    asm("fma.rn.f32x2 %0, %1, %2, %0;" : "+l"(d) : "l"(a), "l"(b));
}
__device__ __forceinline__ u64 add2(u64 a, u64 b) {
    u64 r; asm("add.rn.f32x2 %0, %1, %2;" : "=l"(r) : "l"(a), "l"(b)); return r;
}
__device__ __forceinline__ float hsum2(u64 a, u64 b) {
    u64 s = add2(a, b);
    float lo, hi;
    asm("mov.b64 {%0,%1}, %2;" : "=f"(lo), "=f"(hi) : "l"(s));
    return lo + hi;
}
__device__ __forceinline__ float fast_tanh(float x) {
    float e = __expf(2.0f * x);
    return 1.0f - __fdividef(2.0f, e + 1.0f);
}
// Group barrier: syncs the 128 threads (4 warps) of one row-group.
__device__ __forceinline__ void bar_grp(int g) {
    asm volatile("bar.sync %0, 128;" :: "r"(g + 1) : "memory");
}

// ---------------------------------------------------------------------------
// Kernel 1: fold embedding + layer-0 input projection into a 500x64 LUT.
// ---------------------------------------------------------------------------
__global__ void xproj_kernel(const float* __restrict__ emb,
                             const float* __restrict__ W_ih0,
                             const float* __restrict__ b_ih0) {
    __shared__ float se[EMB];
    const int v = blockIdx.x;
    const int i = threadIdx.x;
    se[i] = emb[v * EMB + i];
    __syncthreads();
    float acc = 0.0f;
    const float4* wr = (const float4*)(W_ih0 + i * EMB);
    #pragma unroll
    for (int q = 0; q < 16; q++) {
        float4 wv = __ldg(wr + q);
        acc += wv.x * se[4*q+0] + wv.y * se[4*q+1] + wv.z * se[4*q+2] + wv.w * se[4*q+3];
    }
    g_xproj[v * HID + i] = acc + b_ih0[i];
}

// ---------------------------------------------------------------------------
// Kernel 2: sequential scan. CTA = 256 threads = 2 groups x 128; grid = 128
// (1 CTA/SM). Within a group, lane pairs split the j-range (jh = lane&1,
// i = gt>>1): weight rows are 3 x 32 floats = 96 regs -> ~165 regs total,
// NO spill (the 192-reg designs of R3/R6/R7 all spilled). Each thread runs
// TWO interleaved batch rows (weights are row-independent), giving 12
// independent fma2 chains per step and amortizing each barrier over 2 rows.
// One merged fma region per step computes Wih1*h1_t, Whh0*h1_t (next step)
// and Whh1*h2_{t-1}; j-halves reduce via shfl_xor(1). h2 double-buffered;
// h1 single-buffered. h arrays padded (upper half at +36 floats) so the two
// LDS.128 addresses per warp hit disjoint banks. Index dtype (int64/int32)
// detected from the GLOBAL first 128 words (in-bounds for both layouts).
// ---------------------------------------------------------------------------
__global__ void __launch_bounds__(256, 1)
scan_kernel(const int* __restrict__ xw,
            const float* __restrict__ W_hh0,
            const float* __restrict__ b_hh0,
            const float* __restrict__ W_ih1,
            const float* __restrict__ W_hh1,
            const float* __restrict__ b_ih1,
            const float* __restrict__ b_hh1,
            const float* __restrict__ fc_w,
            const float* __restrict__ fc_b,
            float* __restrict__ out) {
    __shared__ __align__(16) float sh1[ROWS_PER_CTA][HPAD];
    __shared__ __align__(16) float sh2[2][ROWS_PER_CTA][HPAD];
    __shared__ int   sidx[ROWS_PER_CTA * SEQ];
    __shared__ float swsum[ROWS_PER_CTA][4];
    __shared__ int   s_is64;

    const int tid  = threadIdx.x;
    const int g    = tid >> 7;            // row-group 0/1
    const int gt   = tid & 127;
    const int i    = gt >> 1;             // owned output 0..63
    const int jh   = gt & 1;              // j-half selector
    const int lane = tid & 31;
    const int wing = (tid >> 5) & 3;      // warp within group (0..3)
    const int rbase = blockIdx.x * ROWS_PER_CTA;
    const int A = g * 2, B = g * 2 + 1;   // local row-streams
    const int iw = i + ((i >> 5) << 2);   // padded write index
    const int jbase = jh * 32;
    const int hoff  = jh * 36;            // padded read offset (144B, 16B-aligned)

    // --- weights: row i, own j-half, as f32x2 pairs (3 x 16 u64 = 96 regs) ---
    u64 w0[16], w1[16], w2[16];           // W_hh0, W_ih1, W_hh1
    {
        const u64* q0 = (const u64*)(W_hh0 + i * HID + jbase);
        const u64* q1 = (const u64*)(W_ih1 + i * HID + jbase);
        const u64* q2 = (const u64*)(W_hh1 + i * HID + jbase);
        #pragma unroll
        for (int q = 0; q < 16; q++) {
            w0[q] = __ldg(q0 + q);
            w1[q] = __ldg(q1 + q);
            w2[q] = __ldg(q2 + q);
        }
    }
    const float bia1 = b_hh0[i];
    const float bia2 = b_ih1[i] + b_hh1[i];

    // --- dtype probe on GLOBAL first 128 words (valid for either layout) ---
    if (tid == 0) {
        int z = 0;
        #pragma unroll
        for (int k = 1; k < 128; k += 2) z |= xw[k];
        s_is64 = (z == 0);
    }
    // zero h2 double buffers
    for (int k = tid; k < 2 * ROWS_PER_CTA * HPAD; k += 256)
        (&sh2[0][0][0])[k] = 0.0f;
    __syncthreads();
    {
        const int is64 = s_is64;
        const int base = rbase * SEQ;
        for (int k = tid; k < ROWS_PER_CTA * SEQ; k += 256) {
            int v = is64 ? xw[2 * (base + k)] : xw[base + k];
            sidx[k] = min(max(v, 0), VOCAB - 1);
        }
    }
    __syncthreads();

    const int* ixA = sidx + A * SEQ;
    const int* ixB = sidx + B * SEQ;
    const ulonglong2* H1A = (const ulonglong2*)(sh1[A] + hoff);
    const ulonglong2* H1B = (const ulonglong2*)(sh1[B] + hoff);

    // carried state per stream (h[-1] = 0); cq = full Whh0.h1_prev sum
    float cqA = 0.0f, cqB = 0.0f;
    float xnA = __ldg(&g_xproj[ixA[0] * HID + i]);
    float xnB = __ldg(&g_xproj[ixB[0] * HID + i]);
    float h2nA = 0.0f, h2nB = 0.0f;

    #pragma unroll 1
    for (int t = 0; t < SEQ; t++) {
        const float xcA = xnA, xcB = xnB;
        const int tn = (t + 1 < SEQ) ? (t + 1) : (SEQ - 1);
        xnA = __ldg(&g_xproj[ixA[tn] * HID + i]);
        xnB = __ldg(&g_xproj[ixB[tn] * HID + i]);

        // h1_t = tanh(Whh0.h1_{t-1} + x_t + b1)  (redundant across the pair)
        const float h1A = fast_tanh(cqA + xcA + bia1);
        const float h1B = fast_tanh(cqB + xcB + bia1);
        if (jh == 0) { sh1[A][iw] = h1A; sh1[B][iw] = h1B; }
        bar_grp(g);   // B1: h1_t visible to the whole group

        // merged region: s = Wih1.h1_t, q = Whh0.h1_t (next step),
        //                r = Whh1.h2_{t-1}  — 12 independent chains
        const ulonglong2* H2A = (const ulonglong2*)(sh2[t & 1][A] + hoff);
        const ulonglong2* H2B = (const ulonglong2*)(sh2[t & 1][B] + hoff);
        u64 sA0 = 0, sA1 = 0, qA0 = 0, qA1 = 0, rA0 = 0, rA1 = 0;
        u64 sB0 = 0, sB1 = 0, qB0 = 0, qB1 = 0, rB0 = 0, rB1 = 0;
        #pragma unroll
        for (int m = 0; m < 8; m++) {
            ulonglong2 ha = H1A[m];
            fma2(sA0, w1[2*m], ha.x); fma2(sA1, w1[2*m+1], ha.y);
            fma2(qA0, w0[2*m], ha.x); fma2(qA1, w0[2*m+1], ha.y);
            ulonglong2 ga = H2A[m];
            fma2(rA0, w2[2*m], ga.x); fma2(rA1, w2[2*m+1], ga.y);
            ulonglong2 hb = H1B[m];
            fma2(sB0, w1[2*m], hb.x); fma2(sB1, w1[2*m+1], hb.y);
            fma2(qB0, w0[2*m], hb.x); fma2(qB1, w0[2*m+1], hb.y);
            ulonglong2 gb = H2B[m];
            fma2(rB0, w2[2*m], gb.x); fma2(rB1, w2[2*m+1], gb.y);
        }
        // half-sums -> full sums via in-pair butterfly (both lanes get all)
        float sA = hsum2(sA0, sA1); sA += __shfl_xor_sync(0xffffffffu, sA, 1);
        float rA = hsum2(rA0, rA1); rA += __shfl_xor_sync(0xffffffffu, rA, 1);
        cqA = hsum2(qA0, qA1);     cqA += __shfl_xor_sync(0xffffffffu, cqA, 1);
        float sB = hsum2(sB0, sB1); sB += __shfl_xor_sync(0xffffffffu, sB, 1);
        float rB = hsum2(rB0, rB1); rB += __shfl_xor_sync(0xffffffffu, rB, 1);
        cqB = hsum2(qB0, qB1);     cqB += __shfl_xor_sync(0xffffffffu, cqB, 1);

        // h2_t = tanh(Wih1.h1_t + Whh1.h2_{t-1} + b2) -> opposite buffer
        h2nA = fast_tanh(sA + rA + bia2);
        h2nB = fast_tanh(sB + rB + bia2);
        if (jh == 0) {
            sh2[(t + 1) & 1][A][iw] = h2nA;
            sh2[(t + 1) & 1][B][iw] = h2nB;
        }
        bar_grp(g);   // B2: h2_t visible
    }

    // --- final projection: out[b] = fc_w . h2 + fc_b ---
    const float fw = __ldg(&fc_w[i]);
    float vA = (jh == 0) ? fw * h2nA : 0.0f;
    float vB = (jh == 0) ? fw * h2nB : 0.0f;
    #pragma unroll
    for (int off = 16; off; off >>= 1) {
        vA += __shfl_xor_sync(0xffffffffu, vA, off);
        vB += __shfl_xor_sync(0xffffffffu, vB, off);
    }
    if (lane == 0) { swsum[A][wing] = vA; swsum[B][wing] = vB; }
    __syncthreads();
    if (tid < ROWS_PER_CTA)
        out[rbase + tid] = swsum[tid][0] + swsum[tid][1] +
                           swsum[tid][2] + swsum[tid][3] + fc_b[0];
}

// ---------------------------------------------------------------------------
extern "C" void kernel_launch(void* const* d_in, const int* in_sizes, int n_in,
                              void* d_out, int out_size) {
    const int*   x_raw = (const int*)d_in[0];
    const float* emb   = (const float*)d_in[1];
    const float* W_ih0 = (const float*)d_in[2];
    const float* W_hh0 = (const float*)d_in[3];
    const float* b_ih0 = (const float*)d_in[4];
    const float* b_hh0 = (const float*)d_in[5];
    const float* W_ih1 = (const float*)d_in[6];
    const float* W_hh1 = (const float*)d_in[7];
    const float* b_ih1 = (const float*)d_in[8];
    const float* b_hh1 = (const float*)d_in[9];
    const float* fc_w  = (const float*)d_in[10];
    const float* fc_b  = (const float*)d_in[11];
    float*       out   = (float*)d_out;

    xproj_kernel<<<VOCAB, HID>>>(emb, W_ih0, b_ih0);
    scan_kernel<<<BATCH / ROWS_PER_CTA, 256>>>(
        x_raw, W_hh0, b_hh0, W_ih1, W_hh1, b_ih1, b_hh1, fc_w, fc_b, out);
}

// round 9
// speedup vs baseline: 1.1430x; 1.1430x over previous
#include <cuda_runtime.h>

#define VOCAB 500
#define EMB   64
#define HID   64
#define BATCH 512
#define SEQ   512
#define ROWS_PER_CTA 4
#define HPAD  68          // padded h row: [0..31] jh0, [36..67] jh1

// Precomputed input projection: E'[v][i] = b_ih0[i] + sum_j emb[v][j]*W_ih0[i][j]
__device__ float g_xproj[VOCAB * HID];

typedef unsigned long long u64;

__device__ __forceinline__ void fma2(u64 &d, u64 a, u64 b) {
    asm("fma.rn.f32x2 %0, %1, %2, %0;" : "+l"(d) : "l"(a), "l"(b));
}
__device__ __forceinline__ float hsum1(u64 a) {
    float lo, hi;
    asm("mov.b64 {%0,%1}, %2;" : "=f"(lo), "=f"(hi) : "l"(a));
    return lo + hi;
}
__device__ __forceinline__ float fast_tanh(float x) {
    float e = __expf(2.0f * x);
    return 1.0f - __fdividef(2.0f, e + 1.0f);
}
// Row barrier: syncs the 128 threads (4 warps) of one row.
__device__ __forceinline__ void bar_row(int row) {
    asm volatile("bar.sync %0, 128;" :: "r"(row + 1) : "memory");
}

// ---------------------------------------------------------------------------
// Kernel 1: fold embedding + layer-0 input projection into a 500x64 LUT.
// ---------------------------------------------------------------------------
__global__ void xproj_kernel(const float* __restrict__ emb,
                             const float* __restrict__ W_ih0,
                             const float* __restrict__ b_ih0) {
    __shared__ float se[EMB];
    const int v = blockIdx.x;
    const int i = threadIdx.x;
    se[i] = emb[v * EMB + i];
    __syncthreads();
    float acc = 0.0f;
    const float4* wr = (const float4*)(W_ih0 + i * EMB);
    #pragma unroll
    for (int q = 0; q < 16; q++) {
        float4 wv = __ldg(wr + q);
        acc += wv.x * se[4*q+0] + wv.y * se[4*q+1] + wv.z * se[4*q+2] + wv.w * se[4*q+3];
    }
    g_xproj[v * HID + i] = acc + b_ih0[i];
}

// ---------------------------------------------------------------------------
// Kernel 2: sequential scan. CTA = 512 threads = 4 rows x 128; grid = 128.
// Regfile forces exactly 1 CTA/SM (512 x 128 regs = 64K) -> one wave, and
// each SMSP carries 4 warps belonging to 4 independently-synced rows.
// Thread = (row, i, jh): owns output i with j-half jh. Weights: 3 x 32
// floats = 96 regs -> total demand ~125 under the 128 cap (spill-safe by
// construction; every >=192-weight-reg design spilled: R3/R6/R7/R8).
// ONE named barrier per step: both h1 and h2 are double-buffered, so the
// write->read and read->overwrite races are each separated by exactly one
// barrier interval. Merged fma region (s = Wih1.h1_t, q = Whh0.h1_t for the
// next step, r = Whh1.h2_{t-1}) uses 3 round-robin accumulators; j-halves
// combine via one shfl_xor(1) per dot product.
// ---------------------------------------------------------------------------
__global__ void __launch_bounds__(512, 1)
scan_kernel(const int* __restrict__ xw,
            const float* __restrict__ W_hh0,
            const float* __restrict__ b_hh0,
            const float* __restrict__ W_ih1,
            const float* __restrict__ W_hh1,
            const float* __restrict__ b_ih1,
            const float* __restrict__ b_hh1,
            const float* __restrict__ fc_w,
            const float* __restrict__ fc_b,
            float* __restrict__ out) {
    __shared__ __align__(16) float sh1[2][ROWS_PER_CTA][HPAD];
    __shared__ __align__(16) float sh2[2][ROWS_PER_CTA][HPAD];
    __shared__ int   sidx[ROWS_PER_CTA * SEQ];
    __shared__ float swsum[ROWS_PER_CTA][4];
    __shared__ int   s_is64;

    const int tid  = threadIdx.x;
    const int row  = tid >> 7;            // 0..3
    const int gt   = tid & 127;
    const int i    = gt >> 1;             // owned output 0..63
    const int jh   = gt & 1;              // j-half selector
    const int rbase = blockIdx.x * ROWS_PER_CTA;
    const int iw   = i + ((i >> 5) << 2); // padded write index
    const int hoff = jh * 36;             // padded read offset (144B, 16B-aligned)

    // --- weights: row i, own j-half, f32x2 pairs (3 x 16 u64 = 96 regs) ---
    u64 w0[16], w1[16], w2[16];           // W_hh0, W_ih1, W_hh1
    {
        const int jbase = jh * 32;
        const u64* q0 = (const u64*)(W_hh0 + i * HID + jbase);
        const u64* q1 = (const u64*)(W_ih1 + i * HID + jbase);
        const u64* q2 = (const u64*)(W_hh1 + i * HID + jbase);
        #pragma unroll
        for (int q = 0; q < 16; q++) {
            w0[q] = __ldg(q0 + q);
            w1[q] = __ldg(q1 + q);
            w2[q] = __ldg(q2 + q);
        }
    }
    const float bia1 = b_hh0[i];
    const float bia2 = b_ih1[i] + b_hh1[i];

    // --- dtype probe on GLOBAL first 128 words (valid for either layout) ---
    if (tid == 0) {
        int z = 0;
        #pragma unroll
        for (int k = 1; k < 128; k += 2) z |= xw[k];
        s_is64 = (z == 0);
    }
    // zero h buffers
    for (int k = tid; k < 2 * ROWS_PER_CTA * HPAD; k += 512) {
        (&sh1[0][0][0])[k] = 0.0f;
        (&sh2[0][0][0])[k] = 0.0f;
    }
    __syncthreads();
    {
        const int is64 = s_is64;
        const int base = rbase * SEQ;
        for (int k = tid; k < ROWS_PER_CTA * SEQ; k += 512) {
            int v = is64 ? xw[2 * (base + k)] : xw[base + k];
            sidx[k] = min(max(v, 0), VOCAB - 1);
        }
    }
    __syncthreads();

    const int* my_ix = sidx + row * SEQ;
    float cq  = 0.0f;                      // Whh0 . h1_prev (full sum)
    float xn  = __ldg(&g_xproj[my_ix[0] * HID + i]);
    float h2n = 0.0f;

    #pragma unroll 1
    for (int t = 0; t < SEQ; t++) {
        const int cur = t & 1;
        const float xc = xn;
        const int tn = (t + 1 < SEQ) ? (t + 1) : (SEQ - 1);
        xn = __ldg(&g_xproj[my_ix[tn] * HID + i]);   // prefetch next input

        // h1_t = tanh(Whh0.h1_{t-1} + x_t + b1)   (redundant across pair)
        const float h1n = fast_tanh(cq + xc + bia1);
        if (jh == 0) sh1[cur][row][iw] = h1n;
        bar_row(row);   // the ONLY barrier in the step

        // merged region: s = Wih1.h1_t, q = Whh0.h1_t, r = Whh1.h2_{t-1}
        const ulonglong2* H1 = (const ulonglong2*)(sh1[cur][row] + hoff);
        const ulonglong2* H2 = (const ulonglong2*)(sh2[cur ^ 1][row] + hoff);
        u64 s0 = 0, q0 = 0, r0 = 0;
        #pragma unroll
        for (int m = 0; m < 8; m++) {
            ulonglong2 ha = H1[m];
            ulonglong2 ga = H2[m];
            fma2(s0, w1[2*m],   ha.x);
            fma2(q0, w0[2*m],   ha.x);
            fma2(r0, w2[2*m],   ga.x);
            fma2(s0, w1[2*m+1], ha.y);
            fma2(q0, w0[2*m+1], ha.y);
            fma2(r0, w2[2*m+1], ga.y);
        }
        float s = hsum1(s0);  s  += __shfl_xor_sync(0xffffffffu, s,  1);
        float r = hsum1(r0);  r  += __shfl_xor_sync(0xffffffffu, r,  1);
        cq      = hsum1(q0);  cq += __shfl_xor_sync(0xffffffffu, cq, 1);

        // h2_t = tanh(Wih1.h1_t + Whh1.h2_{t-1} + b2) -> buffer cur
        h2n = fast_tanh(s + r + bia2);
        if (jh == 0) sh2[cur][row][iw] = h2n;
        // no second barrier: next step's bar_row orders this write before
        // its readers, and this step's H2 reads before its overwrite at t+2.
    }

    // --- final projection: out[b] = fc_w . h2 + fc_b ---
    const float fw = __ldg(&fc_w[i]);
    float val = (jh == 0) ? fw * h2n : 0.0f;
    #pragma unroll
    for (int off = 16; off; off >>= 1)
        val += __shfl_xor_sync(0xffffffffu, val, off);
    const int wing = (tid >> 5) & 3;
    if ((tid & 31) == 0) swsum[row][wing] = val;
    __syncthreads();
    if (tid < ROWS_PER_CTA)
        out[rbase + tid] = swsum[tid][0] + swsum[tid][1] +
                           swsum[tid][2] + swsum[tid][3] + fc_b[0];
}

// ---------------------------------------------------------------------------
extern "C" void kernel_launch(void* const* d_in, const int* in_sizes, int n_in,
                              void* d_out, int out_size) {
    const int*   x_raw = (const int*)d_in[0];
    const float* emb   = (const float*)d_in[1];
    const float* W_ih0 = (const float*)d_in[2];
    const float* W_hh0 = (const float*)d_in[3];
    const float* b_ih0 = (const float*)d_in[4];
    const float* b_hh0 = (const float*)d_in[5];
    const float* W_ih1 = (const float*)d_in[6];
    const float* W_hh1 = (const float*)d_in[7];
    const float* b_ih1 = (const float*)d_in[8];
    const float* b_hh1 = (const float*)d_in[9];
    const float* fc_w  = (const float*)d_in[10];
    const float* fc_b  = (const float*)d_in[11];
    float*       out   = (float*)d_out;

    xproj_kernel<<<VOCAB, HID>>>(emb, W_ih0, b_ih0);
    scan_kernel<<<BATCH / ROWS_PER_CTA, 512>>>(
        x_raw, W_hh0, b_hh0, W_ih1, W_hh1, b_ih1, b_hh1, fc_w, fc_b, out);
}